// round 8
// baseline (speedup 1.0000x reference)
#include <cuda_runtime.h>

// Problem constants (fixed by the dataset)
#define Nn  64      // waveguides
#define Dd  8       // decomp
#define Ww  128     // wavelengths
#define Bb  512     // batch
#define Kk  64      // chain depth

// ---------------------------------------------------------------------------
// Guarded global load (float index space): never faults.
// ---------------------------------------------------------------------------
__device__ __forceinline__ float gldf(const float* __restrict__ p,
                                      long long i, long long n)
{
    return (p && i >= 0 && i < n) ? p[i] : 0.0f;
}

// Accurate sincos for large args even under fast-math: Cody-Waite mod 2*pi.
__device__ __forceinline__ void safe_sincos(float a, float* s, float* c)
{
    float n = rintf(a * 0.15915494309189535f);
    float r = fmaf(n, -6.2831855f, a);       // a - n*fl32(2pi)
    r = fmaf(n, 1.7484556e-7f, r);           // - n*(2pi - fl32(2pi))
    sincosf(r, s, c);
}

__device__ __forceinline__ float2 cmul(float2 a, float2 b)
{
    return make_float2(fmaf(a.x, b.x, -a.y * b.y),
                       fmaf(a.x, b.y,  a.y * b.x));
}

// ---------------------------------------------------------------------------
// Probe kernel (binding-failure branch): safe under any out_size unit.
// ---------------------------------------------------------------------------
__global__ void pic_probe(float* __restrict__ outf, long long n)
{
    long long i = (long long)blockIdx.x * blockDim.x + threadIdx.x;
    if (i < n) outf[i] = 0.0f;
}

// ---------------------------------------------------------------------------
// Fused kernel: one CTA per (d,w).
//   Phase A: Ms = T_0 @ ... @ T_{K-1} in smem, T_k = C @ diag(t_k).
//   Phase B: out[b,:] = Ms @ x[b,:], 16 batch rows at a time.
// Output layout:
//   interleaved==0 : outf[g]            = Re(out[g])     (float32 output)
//   interleaved==1 : outf[2g], outf[2g+1] = Re, Im       (complex floats)
// All global accesses bounds-guarded by matched capacities.
// ---------------------------------------------------------------------------
__global__ void __launch_bounds__(256)
pic_fused(const float* __restrict__ vals, long long nv,   // float capacity
          const float* __restrict__ wls,  long long nw,
          const float* __restrict__ xr,   long long nxr,
          const float* __restrict__ xi,   long long nxi,
          int xstride,
          float*       __restrict__ outf, long long nof,  // float capacity
          int interleaved)
{
    __shared__ float2 Ms[Nn * Nn];      // 32768 B
    __shared__ float2 Xs[16 * 65];      // 8320 B

    const int w   = blockIdx.x;
    const int d   = blockIdx.y;
    const int tid = threadIdx.x;
    const int ty  = tid >> 4;           // 0..15
    const int tx  = tid & 15;           // 0..15
    const float wl = gldf(wls, w, nw);

    // Per-thread C-column state for columns n_c = tx + 16*c
    const float CANG = -0.09817477042468103f;   // fl(-2*pi/64)
    float2 stepc[4], pre16[4], pre32[4], pre48[4];
    #pragma unroll
    for (int c = 0; c < 4; c++) {
        int n = tx + 16 * c;
        float s0, c0;
        safe_sincos(__fmul_rn(CANG, (float)n), &s0, &c0);
        stepc[c] = make_float2(c0, s0);
        safe_sincos(__fmul_rn(CANG, (float)(16 * n)), &s0, &c0);
        pre16[c] = make_float2(0.125f * c0, 0.125f * s0);
        safe_sincos(__fmul_rn(CANG, (float)(32 * n)), &s0, &c0);
        pre32[c] = make_float2(0.125f * c0, 0.125f * s0);
        safe_sincos(__fmul_rn(CANG, (float)(48 * n)), &s0, &c0);
        pre48[c] = make_float2(0.125f * c0, 0.125f * s0);
    }

    // Ms = Identity (reference: M0 = I)
    for (int idx = tid; idx < Nn * Nn; idx += 256) {
        int i = idx >> 6, j = idx & 63;
        Ms[idx & (Nn * Nn - 1)] = make_float2((i == j) ? 1.0f : 0.0f, 0.0f);
    }

    // =================== Phase A: build transfer matrix ===================
    for (int k = 0; k < Kk; ++k) {
        float2 tsr[4];
        #pragma unroll
        for (int c = 0; c < 4; c++) {
            int n = tx + 16 * c;
            float Ln  = __fmul_rn(31.415926535897931f,
                        __fadd_rn(1.0f, __fmul_rn(0.01f, (float)n)));
            float v   = gldf(vals, (long long)(k * Dd + d) * Nn + n, nv);
            float phi = __fadd_rn(
                __fmul_rn(15.079644737231007f, __fdiv_rn(Ln, wl)),
                __fmul_rn(6.2831853071795862f, v));
            float s, cc;
            safe_sincos(phi, &s, &cc);
            float nr = __fsub_rn(0.95f, __fmul_rn(0.99f, cc));
            float ni = -__fmul_rn(0.99f, s);
            float dr = __fsub_rn(1.0f, __fmul_rn(0.9405f, cc));
            float di = -__fmul_rn(0.9405f, s);
            float inv = 1.0f / (dr * dr + di * di);
            tsr[c] = make_float2((nr * dr + ni * di) * inv,
                                 (ni * dr - nr * di) * inv);
        }

        float2 acc[4][4];
        #pragma unroll
        for (int m = 0; m < 4; m++)
            #pragma unroll
            for (int c = 0; c < 4; c++)
                acc[m][c] = make_float2(0.f, 0.f);

        __syncthreads();   // Ms ready (identity or previous write-back)

        float2 cw[4];
        for (int j = 0; j < Nn; ++j) {
            // C[j][n_c]: exact reset every 16 rows, twiddle recurrence between
            if (j == 0) {
                #pragma unroll
                for (int c = 0; c < 4; c++) cw[c] = make_float2(0.125f, 0.f);
            } else if (j == 16) {
                #pragma unroll
                for (int c = 0; c < 4; c++) cw[c] = pre16[c];
            } else if (j == 32) {
                #pragma unroll
                for (int c = 0; c < 4; c++) cw[c] = pre32[c];
            } else if (j == 48) {
                #pragma unroll
                for (int c = 0; c < 4; c++) cw[c] = pre48[c];
            } else {
                #pragma unroll
                for (int c = 0; c < 4; c++) cw[c] = cmul(cw[c], stepc[c]);
            }

            float2 mr[4];
            #pragma unroll
            for (int m = 0; m < 4; m++)       // 2-address broadcast loads
                mr[m] = Ms[((ty + 16 * m) * Nn + j) & (Nn * Nn - 1)];
            #pragma unroll
            for (int m = 0; m < 4; m++)
                #pragma unroll
                for (int c = 0; c < 4; c++) {
                    acc[m][c].x = fmaf( mr[m].x, cw[c].x, acc[m][c].x);
                    acc[m][c].x = fmaf(-mr[m].y, cw[c].y, acc[m][c].x);
                    acc[m][c].y = fmaf( mr[m].x, cw[c].y, acc[m][c].y);
                    acc[m][c].y = fmaf( mr[m].y, cw[c].x, acc[m][c].y);
                }
        }

        __syncthreads();   // all Ms reads for this k complete
        #pragma unroll
        for (int m = 0; m < 4; m++)
            #pragma unroll
            for (int c = 0; c < 4; c++) {
                float2 t = tsr[c];
                Ms[((ty + 16 * m) * Nn + (tx + 16 * c)) & (Nn * Nn - 1)] =
                    make_float2(acc[m][c].x * t.x - acc[m][c].y * t.y,
                                acc[m][c].x * t.y + acc[m][c].y * t.x);
            }
    }
    __syncthreads();       // final Ms visible to all

    // =================== Phase B: apply to batch ==========================
    for (int bt = 0; bt < Bb / 16; ++bt) {
        for (int idx = tid; idx < 16 * Nn; idx += 256) {
            int r = idx >> 6, j = idx & 63;
            long long b = (long long)bt * 16 + r;
            long long g = ((b * Dd + d) * Ww + w) * Nn + j;
            Xs[r * 65 + j] = make_float2(gldf(xr, g * xstride, nxr),
                                         gldf(xi, g * xstride, nxi));
        }
        __syncthreads();

        float2 acc[4];
        #pragma unroll
        for (int c = 0; c < 4; c++) acc[c] = make_float2(0.f, 0.f);

        #pragma unroll 2
        for (int jj = 0; jj < Nn; ++jj) {
            int j = (jj + tx) & 63;               // rotated: conflict-free Ms
            float2 xv = Xs[ty * 65 + j];
            float2 mv[4];
            #pragma unroll
            for (int c = 0; c < 4; c++)
                mv[c] = Ms[((tx + 16 * c) * Nn + j) & (Nn * Nn - 1)];
            #pragma unroll
            for (int c = 0; c < 4; c++) {
                acc[c].x = fmaf( xv.x, mv[c].x, acc[c].x);
                acc[c].x = fmaf(-xv.y, mv[c].y, acc[c].x);
                acc[c].y = fmaf( xv.x, mv[c].y, acc[c].y);
                acc[c].y = fmaf( xv.y, mv[c].x, acc[c].y);
            }
        }

        #pragma unroll
        for (int c = 0; c < 4; c++) {
            long long b = (long long)bt * 16 + ty;
            int i = tx + 16 * c;
            long long g = ((b * Dd + d) * Ww + w) * Nn + i;
            if (interleaved) {
                if (2 * g + 1 < nof) {
                    outf[2 * g + 0] = acc[c].x;
                    outf[2 * g + 1] = acc[c].y;
                }
            } else {
                if (g < nof) outf[g] = acc[c].x;   // real part only
            }
        }
        __syncthreads();
    }
}

// ---------------------------------------------------------------------------
extern "C" void kernel_launch(void* const* d_in, const int* in_sizes, int n_in,
                              void* d_out, int out_size)
{
    const long long NX = (long long)Bb * Dd * Ww * Nn;   // 33,554,432
    const long long NV = (long long)Kk * Dd * Nn;        // 32,768
    const long long NW = Ww;                             // 128

    const float *x0 = 0, *x1 = 0, *vals = 0, *wls = 0;
    long long nx0 = 0, nx1 = 0, nv = 0, nw = 0;          // float capacities
    int xcomplex = 0;

    // Size-evidence binding only. pass 0: element counts; pass 1: byte counts.
    for (int pass = 0; pass < 2; ++pass) {
        long long mul = (pass == 0) ? 1 : 4;
        x0 = x1 = vals = wls = 0; nx0 = nx1 = nv = nw = 0; xcomplex = 0;
        int nxbuf = 0;
        for (int i = 0; i < n_in; i++) {
            long long s = (long long)in_sizes[i];
            const float* p = (const float*)d_in[i];
            if (!p) continue;
            if (s == NX * mul) {                 // float plane (x_real first)
                if (nxbuf == 0) { x0 = p; nx0 = NX; nxbuf = 1; }
                else if (nxbuf == 1) { x1 = p; nx1 = NX; nxbuf = 2; }
            } else if (s == 2 * NX * mul) {      // interleaved complex floats
                x0 = p; nx0 = 2 * NX; nxbuf = 2; xcomplex = 1;
            } else if (s == NV * mul) { if (!vals) { vals = p; nv = NV; } }
            else if (s == NW * mul)   { if (!wls)  { wls  = p; nw = NW; } }
        }
        if (nxbuf == 1 && vals && wls) {         // single NX-elem buffer:
            xcomplex = 1; nx0 = 2 * NX; x1 = 0; nxbuf = 2;   // complex64 view
        }
        if (nxbuf == 2 && vals && wls) break;
        x0 = 0;
    }

    if (!(x0 && vals && wls) || !d_out) {
        // Binding failed: probe (writes <= out_size/4 floats, safe everywhere)
        long long n = (out_size > 4) ? (long long)out_size / 4 : 1;
        pic_probe<<<(unsigned)((n + 255) / 256), 256>>>((float*)d_out, n);
        return;
    }

    // Output convention (deduced R1-R7): d_out capacity is out_size FLOATS
    // when out_size == NX (float32 real-part output). Interleaved complex
    // only when out_size == 2*NX exactly.
    int interleaved;
    long long n_floats;
    if ((long long)out_size == 2 * NX) { interleaved = 1; n_floats = 2 * NX; }
    else { interleaved = 0;
           n_floats = ((long long)out_size < NX) ? (long long)out_size : NX; }

    const float* xr;  const float* xi;  long long nxr, nxi;  int xstride;
    if (xcomplex) { xr = x0; nxr = nx0; xi = x0 + 1; nxi = nx0 - 1; xstride = 2; }
    else          { xr = x0; nxr = nx0; xi = x1;     nxi = nx1;     xstride = 1; }

    dim3 grid(Ww, Dd);
    pic_fused<<<grid, 256>>>(vals, nv, wls, nw,
                             xr, nxr, xi, nxi, xstride,
                             (float*)d_out, n_floats, interleaved);
}

// round 9
// speedup vs baseline: 4.0925x; 4.0925x over previous
#include <cuda_runtime.h>

// Problem constants (fixed by the dataset)
#define Nn  64      // waveguides
#define Dd  8       // decomp
#define Ww  128     // wavelengths
#define Bb  512     // batch
#define Kk  64      // chain depth
#define Sd  65      // padded row stride (float2 units) -> <=2-way smem conflicts

// Dynamic smem: Ms[64*Sd] + Ex[64*Sd] + tS[64]
#define SMEM_F2    (2 * Nn * Sd + Nn)
#define SMEM_BYTES (SMEM_F2 * (int)sizeof(float2))   // 67072 B

// ---------------------------------------------------------------------------
__device__ __forceinline__ float gldf(const float* __restrict__ p,
                                      long long i, long long n)
{
    return (p && i >= 0 && i < n) ? p[i] : 0.0f;
}

// Accurate sincos under fast-math: Cody-Waite mod 2*pi, then sincosf.
__device__ __forceinline__ void safe_sincos(float a, float* s, float* c)
{
    float n = rintf(a * 0.15915494309189535f);
    float r = fmaf(n, -6.2831855f, a);
    r = fmaf(n, 1.7484556e-7f, r);
    sincosf(r, s, c);
}

__device__ __forceinline__ float2 cmul(float2 a, float2 b)
{
    return make_float2(fmaf(a.x, b.x, -a.y * b.y),
                       fmaf(a.x, b.y,  a.y * b.x));
}

// Radix-4 DIF kernel: o_r = sum_{j2} in_{j2} * (-i)^{j2*r}
__device__ __forceinline__ void bfly4(float2 a, float2 b, float2 c, float2 d,
                                      float2& o0, float2& o1,
                                      float2& o2, float2& o3)
{
    float t0x = a.x + c.x, t0y = a.y + c.y;
    float t1x = a.x - c.x, t1y = a.y - c.y;
    float t2x = b.x + d.x, t2y = b.y + d.y;
    float t3x = b.x - d.x, t3y = b.y - d.y;
    o0 = make_float2(t0x + t2x, t0y + t2y);
    o2 = make_float2(t0x - t2x, t0y - t2y);
    o1 = make_float2(t1x + t3y, t1y - t3x);   // t1 - i*t3
    o3 = make_float2(t1x - t3y, t1y + t3x);   // t1 + i*t3
}

// ---------------------------------------------------------------------------
__global__ void pic_probe(float* __restrict__ outf, long long n)
{
    long long i = (long long)blockIdx.x * blockDim.x + threadIdx.x;
    if (i < n) outf[i] = 0.0f;
}

// ---------------------------------------------------------------------------
// Fused kernel, one CTA per (d,w), 256 threads.
// Phase A (build): 64 k-steps of  M <- rowFFT64(M) * diag(0.125*t_k).
//   Thread (q=tid>>6, row=tid&63) owns row elements j == q (mod 4).
//   Radix-4 stages d=16, d=4 in registers; d=1 via one smem exchange.
//   Output written digit-reversed -> natural order for free.
// Phase B (apply): out[b,i] = Re( sum_j M[i,j] x[b,j] ), 16 b-rows/tile.
// ---------------------------------------------------------------------------
__global__ void __launch_bounds__(256, 2)
pic_fused(const float* __restrict__ vals, long long nv,
          const float* __restrict__ wls,  long long nw,
          const float* __restrict__ xr,   long long nxr,
          const float* __restrict__ xi,   long long nxi,
          int xstride,
          float*       __restrict__ outf, long long nof,
          int interleaved)
{
    extern __shared__ float2 sh[];
    float2* Ms = sh;                    // [Nn * Sd]
    float2* Ex = sh + Nn * Sd;          // [Nn * Sd] exchange / later Xs
    float2* tS = sh + 2 * Nn * Sd;      // [Nn] 0.125*t_k

    const int w   = blockIdx.x;
    const int d   = blockIdx.y;
    const int tid = threadIdx.x;
    const int q   = tid >> 6;           // 0..3
    const int row = tid & 63;
    const float wl = gldf(wls, w, nw);

    // Twiddles (precomputed in registers, fixed per thread)
    const float CANG = -0.09817477042468103f;   // fl(-2*pi/64)
    float2 wA[4][3];   // W64^{(q+4e0)*r}, r=1..3
    float2 wB[3];      // W16^{q*s} = W64^{4*q*s}, s=1..3
    #pragma unroll
    for (int e0 = 0; e0 < 4; e0++)
        #pragma unroll
        for (int r = 1; r <= 3; r++) {
            float s0, c0;
            safe_sincos(CANG * (float)((q + 4 * e0) * r), &s0, &c0);
            wA[e0][r - 1] = make_float2(c0, s0);
        }
    #pragma unroll
    for (int s1 = 1; s1 <= 3; s1++) {
        float s0, c0;
        safe_sincos(CANG * (float)(4 * q * s1), &s0, &c0);
        wB[s1 - 1] = make_float2(c0, s0);
    }

    // Ms = Identity
    for (int idx = tid; idx < Nn * Nn; idx += 256) {
        int i = idx >> 6, j = idx & 63;
        Ms[i * Sd + j] = make_float2((i == j) ? 1.0f : 0.0f, 0.0f);
    }
    __syncthreads();

    // =================== Phase A: build ===================
    for (int k = 0; k < Kk; ++k) {
        // Ring response t[n]*0.125 (threads 0..63, n = tid), reference op order
        if (tid < Nn) {
            const int n = tid;
            float Ln  = __fmul_rn(31.415926535897931f,
                        __fadd_rn(1.0f, __fmul_rn(0.01f, (float)n)));
            float v   = gldf(vals, (long long)(k * Dd + d) * Nn + n, nv);
            float phi = __fadd_rn(
                __fmul_rn(15.079644737231007f, __fdiv_rn(Ln, wl)),
                __fmul_rn(6.2831853071795862f, v));
            float s0, c0;
            safe_sincos(phi, &s0, &c0);
            float nr = __fsub_rn(0.95f, __fmul_rn(0.99f, c0));
            float ni = -__fmul_rn(0.99f, s0);
            float dr = __fsub_rn(1.0f, __fmul_rn(0.9405f, c0));
            float di = -__fmul_rn(0.9405f, s0);
            float inv = 1.0f / (dr * dr + di * di);
            tS[n] = make_float2(0.125f * ((nr * dr + ni * di) * inv),
                                0.125f * ((ni * dr - nr * di) * inv));
        }

        // Stage A (d=16): load 16 elems j = q+4e, butterfly over j2, twiddle
        float2 X[16];
        #pragma unroll
        for (int e = 0; e < 16; e++)
            X[e] = Ms[row * Sd + q + 4 * e];

        float2 Y[16];
        #pragma unroll
        for (int e0 = 0; e0 < 4; e0++) {
            float2 o0, o1, o2, o3;
            bfly4(X[e0], X[e0 + 4], X[e0 + 8], X[e0 + 12], o0, o1, o2, o3);
            Y[e0]      = o0;
            Y[4 + e0]  = cmul(o1, wA[e0][0]);
            Y[8 + e0]  = cmul(o2, wA[e0][1]);
            Y[12 + e0] = cmul(o3, wA[e0][2]);
        }

        // Stage B (d=4): butterfly over v, twiddle W16^{q*s}, write exchange
        // Ex slot for z_{r,s}[u=q]:  4*(4s + r) + q
        #pragma unroll
        for (int r = 0; r < 4; r++) {
            float2 o0, o1, o2, o3;
            bfly4(Y[4 * r + 0], Y[4 * r + 1], Y[4 * r + 2], Y[4 * r + 3],
                  o0, o1, o2, o3);
            Ex[row * Sd + 4 * (0      + r) + q] = o0;
            Ex[row * Sd + 4 * (4      + r) + q] = cmul(o1, wB[0]);
            Ex[row * Sd + 4 * (8      + r) + q] = cmul(o2, wB[1]);
            Ex[row * Sd + 4 * (12     + r) + q] = cmul(o3, wB[2]);
        }
        __syncthreads();

        // Stage C (d=1, trivial twiddles): thread q handles s=q, r=0..3.
        // Reads contiguous slots [16q .. 16q+15]; writes n = 16*tau + 4q + r.
        #pragma unroll
        for (int r = 0; r < 4; r++) {
            float2 a  = Ex[row * Sd + 16 * q + 4 * r + 0];
            float2 b  = Ex[row * Sd + 16 * q + 4 * r + 1];
            float2 c2 = Ex[row * Sd + 16 * q + 4 * r + 2];
            float2 d2 = Ex[row * Sd + 16 * q + 4 * r + 3];
            float2 o0, o1, o2, o3;
            bfly4(a, b, c2, d2, o0, o1, o2, o3);
            int n0 = 4 * q + r;
            Ms[row * Sd + n0]      = cmul(o0, tS[n0]);
            Ms[row * Sd + n0 + 16] = cmul(o1, tS[n0 + 16]);
            Ms[row * Sd + n0 + 32] = cmul(o2, tS[n0 + 32]);
            Ms[row * Sd + n0 + 48] = cmul(o3, tS[n0 + 48]);
        }
        __syncthreads();
    }

    // =================== Phase B: apply ===================
    float2* Xs = Ex;                    // reuse exchange buffer
    const int ty = tid >> 4;            // 0..15 batch row in tile
    const int tx = tid & 15;            // output cols {tx, +16, +32, +48}

    for (int bt = 0; bt < Bb / 16; ++bt) {
        for (int idx = tid; idx < 16 * Nn; idx += 256) {
            int r = idx >> 6, j = idx & 63;
            long long b = (long long)bt * 16 + r;
            long long g = ((b * Dd + d) * Ww + w) * Nn + j;
            Xs[r * Sd + j] = make_float2(gldf(xr, g * xstride, nxr),
                                         gldf(xi, g * xstride, nxi));
        }
        __syncthreads();

        float2 acc[4];
        #pragma unroll
        for (int c = 0; c < 4; c++) acc[c] = make_float2(0.f, 0.f);

        #pragma unroll 2
        for (int j = 0; j < Nn; ++j) {
            float2 xv = Xs[ty * Sd + j];            // broadcast (2 addrs/warp)
            float2 mv[4];
            #pragma unroll
            for (int c = 0; c < 4; c++)             // stride-65: conflict-free
                mv[c] = Ms[(tx + 16 * c) * Sd + j];
            #pragma unroll
            for (int c = 0; c < 4; c++) {
                acc[c].x = fmaf( xv.x, mv[c].x, acc[c].x);
                acc[c].x = fmaf(-xv.y, mv[c].y, acc[c].x);
                acc[c].y = fmaf( xv.x, mv[c].y, acc[c].y);
                acc[c].y = fmaf( xv.y, mv[c].x, acc[c].y);
            }
        }

        #pragma unroll
        for (int c = 0; c < 4; c++) {
            long long b = (long long)bt * 16 + ty;
            int i = tx + 16 * c;
            long long g = ((b * Dd + d) * Ww + w) * Nn + i;
            if (interleaved) {
                if (2 * g + 1 < nof) {
                    outf[2 * g + 0] = acc[c].x;
                    outf[2 * g + 1] = acc[c].y;
                }
            } else {
                if (g < nof) outf[g] = acc[c].x;    // real part only
            }
        }
        __syncthreads();
    }
}

// ---------------------------------------------------------------------------
extern "C" void kernel_launch(void* const* d_in, const int* in_sizes, int n_in,
                              void* d_out, int out_size)
{
    const long long NX = (long long)Bb * Dd * Ww * Nn;   // 33,554,432
    const long long NV = (long long)Kk * Dd * Nn;        // 32,768
    const long long NW = Ww;                             // 128

    const float *x0 = 0, *x1 = 0, *vals = 0, *wls = 0;
    long long nx0 = 0, nx1 = 0, nv = 0, nw = 0;
    int xcomplex = 0;

    for (int pass = 0; pass < 2; ++pass) {
        long long mul = (pass == 0) ? 1 : 4;
        x0 = x1 = vals = wls = 0; nx0 = nx1 = nv = nw = 0; xcomplex = 0;
        int nxbuf = 0;
        for (int i = 0; i < n_in; i++) {
            long long s = (long long)in_sizes[i];
            const float* p = (const float*)d_in[i];
            if (!p) continue;
            if (s == NX * mul) {
                if (nxbuf == 0) { x0 = p; nx0 = NX; nxbuf = 1; }
                else if (nxbuf == 1) { x1 = p; nx1 = NX; nxbuf = 2; }
            } else if (s == 2 * NX * mul) {
                x0 = p; nx0 = 2 * NX; nxbuf = 2; xcomplex = 1;
            } else if (s == NV * mul) { if (!vals) { vals = p; nv = NV; } }
            else if (s == NW * mul)   { if (!wls)  { wls  = p; nw = NW; } }
        }
        if (nxbuf == 1 && vals && wls) {
            xcomplex = 1; nx0 = 2 * NX; x1 = 0; nxbuf = 2;
        }
        if (nxbuf == 2 && vals && wls) break;
        x0 = 0;
    }

    if (!(x0 && vals && wls) || !d_out) {
        long long n = (out_size > 4) ? (long long)out_size / 4 : 1;
        pic_probe<<<(unsigned)((n + 255) / 256), 256>>>((float*)d_out, n);
        return;
    }

    // Output: d_out holds out_size FLOATS (real part) unless exactly 2*NX.
    int interleaved;
    long long n_floats;
    if ((long long)out_size == 2 * NX) { interleaved = 1; n_floats = 2 * NX; }
    else { interleaved = 0;
           n_floats = ((long long)out_size < NX) ? (long long)out_size : NX; }

    const float* xrp; const float* xip; long long nxr, nxi; int xstride;
    if (xcomplex) { xrp = x0; nxr = nx0; xip = x0 + 1; nxi = nx0 - 1; xstride = 2; }
    else          { xrp = x0; nxr = nx0; xip = x1;     nxi = nx1;     xstride = 1; }

    cudaFuncSetAttribute(pic_fused, cudaFuncAttributeMaxDynamicSharedMemorySize,
                         SMEM_BYTES);

    dim3 grid(Ww, Dd);
    pic_fused<<<grid, 256, SMEM_BYTES>>>(vals, nv, wls, nw,
                                         xrp, nxr, xip, nxi, xstride,
                                         (float*)d_out, n_floats, interleaved);
}

// round 10
// speedup vs baseline: 7.3872x; 1.8051x over previous
#include <cuda_runtime.h>

// Problem constants (fixed by the dataset)
#define Nn  64      // waveguides
#define Dd  8       // decomp
#define Ww  128     // wavelengths
#define Bb  512     // batch
#define Kk  64      // chain depth
#define Sd  65      // padded row stride (float2) for phase A

// Dynamic smem: Ms[64*Sd] + Ex[64*Sd] + tS[64]  (phase B re-aliases Ex+tS)
#define SMEM_F2    (2 * Nn * Sd + Nn)
#define SMEM_BYTES (SMEM_F2 * (int)sizeof(float2))   // 67072 B

// ---------------------------------------------------------------------------
__device__ __forceinline__ float gldf(const float* __restrict__ p,
                                      long long i, long long n)
{
    return (p && i >= 0 && i < n) ? p[i] : 0.0f;
}

__device__ __forceinline__ void safe_sincos(float a, float* s, float* c)
{
    float n = rintf(a * 0.15915494309189535f);
    float r = fmaf(n, -6.2831855f, a);
    r = fmaf(n, 1.7484556e-7f, r);
    sincosf(r, s, c);
}

__device__ __forceinline__ float2 cmul(float2 a, float2 b)
{
    return make_float2(fmaf(a.x, b.x, -a.y * b.y),
                       fmaf(a.x, b.y,  a.y * b.x));
}

// Packed dual-lane FMA: acc = a*b + acc  (per 32-bit lane), SASS FFMA2.
__device__ __forceinline__ void ffma2(unsigned long long& acc,
                                      unsigned long long a,
                                      unsigned long long b)
{
    asm("fma.rn.f32x2 %0, %1, %2, %0;" : "+l"(acc) : "l"(a), "l"(b));
}

// Radix-4 DIF butterfly
__device__ __forceinline__ void bfly4(float2 a, float2 b, float2 c, float2 d,
                                      float2& o0, float2& o1,
                                      float2& o2, float2& o3)
{
    float t0x = a.x + c.x, t0y = a.y + c.y;
    float t1x = a.x - c.x, t1y = a.y - c.y;
    float t2x = b.x + d.x, t2y = b.y + d.y;
    float t3x = b.x - d.x, t3y = b.y - d.y;
    o0 = make_float2(t0x + t2x, t0y + t2y);
    o2 = make_float2(t0x - t2x, t0y - t2y);
    o1 = make_float2(t1x + t3y, t1y - t3x);
    o3 = make_float2(t1x - t3y, t1y + t3x);
}

// ---------------------------------------------------------------------------
__global__ void pic_probe(float* __restrict__ outf, long long n)
{
    long long i = (long long)blockIdx.x * blockDim.x + threadIdx.x;
    if (i < n) outf[i] = 0.0f;
}

// ---------------------------------------------------------------------------
// One CTA per (d,w), 256 threads.
// Phase A: 64 steps of M <- rowFFT64(M)*diag(0.125*t_k)  (radix-4^3, smem).
// Convert: M -> SoA planes Mre, -Mim (stride 66 floats, conflict-free).
// Phase B: out_re[b,i] = sum_j Mre*xr + (-Mim)*xi, packed f32x2 over j-pairs,
//          4b x 4i register tile per thread, 64-batch tiles.
// ---------------------------------------------------------------------------
__global__ void __launch_bounds__(256, 2)
pic_fused(const float* __restrict__ vals, long long nv,
          const float* __restrict__ wls,  long long nw,
          const float* __restrict__ xr,   long long nxr,
          const float* __restrict__ xi,   long long nxi,
          int xstride,
          float*       __restrict__ outf, long long nof)
{
    extern __shared__ float2 sh[];
    float2* Ms = sh;                    // [64*Sd] float2
    float2* Ex = sh + Nn * Sd;          // [64*Sd] exchange
    float2* tS = sh + 2 * Nn * Sd;      // [64]

    const int w   = blockIdx.x;
    const int d   = blockIdx.y;
    const int tid = threadIdx.x;
    const int q   = tid >> 6;           // 0..3
    const int row = tid & 63;
    const float wl = gldf(wls, w, nw);

    // Twiddles (per-thread constants)
    const float CANG = -0.09817477042468103f;   // fl(-2*pi/64)
    float2 wA[4][3], wB[3];
    #pragma unroll
    for (int e0 = 0; e0 < 4; e0++)
        #pragma unroll
        for (int r = 1; r <= 3; r++) {
            float s0, c0;
            safe_sincos(CANG * (float)((q + 4 * e0) * r), &s0, &c0);
            wA[e0][r - 1] = make_float2(c0, s0);
        }
    #pragma unroll
    for (int s1 = 1; s1 <= 3; s1++) {
        float s0, c0;
        safe_sincos(CANG * (float)(4 * q * s1), &s0, &c0);
        wB[s1 - 1] = make_float2(c0, s0);
    }

    // Ms = Identity
    for (int idx = tid; idx < Nn * Nn; idx += 256) {
        int i = idx >> 6, j = idx & 63;
        Ms[i * Sd + j] = make_float2((i == j) ? 1.0f : 0.0f, 0.0f);
    }
    __syncthreads();

    // =================== Phase A: build ===================
    for (int k = 0; k < Kk; ++k) {
        if (tid < Nn) {
            const int n = tid;
            float Ln  = __fmul_rn(31.415926535897931f,
                        __fadd_rn(1.0f, __fmul_rn(0.01f, (float)n)));
            float v   = gldf(vals, (long long)(k * Dd + d) * Nn + n, nv);
            float phi = __fadd_rn(
                __fmul_rn(15.079644737231007f, __fdiv_rn(Ln, wl)),
                __fmul_rn(6.2831853071795862f, v));
            float s0, c0;
            safe_sincos(phi, &s0, &c0);
            float nr = __fsub_rn(0.95f, __fmul_rn(0.99f, c0));
            float ni = -__fmul_rn(0.99f, s0);
            float dr = __fsub_rn(1.0f, __fmul_rn(0.9405f, c0));
            float di = -__fmul_rn(0.9405f, s0);
            float inv = 1.0f / (dr * dr + di * di);
            tS[n] = make_float2(0.125f * ((nr * dr + ni * di) * inv),
                                0.125f * ((ni * dr - nr * di) * inv));
        }

        // Stage A (stride 16), thread-local
        float2 X[16];
        #pragma unroll
        for (int e = 0; e < 16; e++)
            X[e] = Ms[row * Sd + q + 4 * e];

        float2 Y[16];
        #pragma unroll
        for (int e0 = 0; e0 < 4; e0++) {
            float2 o0, o1, o2, o3;
            bfly4(X[e0], X[e0 + 4], X[e0 + 8], X[e0 + 12], o0, o1, o2, o3);
            Y[e0]      = o0;
            Y[4 + e0]  = cmul(o1, wA[e0][0]);
            Y[8 + e0]  = cmul(o2, wA[e0][1]);
            Y[12 + e0] = cmul(o3, wA[e0][2]);
        }

        // Stage B (stride 4), thread-local -> exchange
        #pragma unroll
        for (int r = 0; r < 4; r++) {
            float2 o0, o1, o2, o3;
            bfly4(Y[4 * r + 0], Y[4 * r + 1], Y[4 * r + 2], Y[4 * r + 3],
                  o0, o1, o2, o3);
            Ex[row * Sd + 4 * (0  + r) + q] = o0;
            Ex[row * Sd + 4 * (4  + r) + q] = cmul(o1, wB[0]);
            Ex[row * Sd + 4 * (8  + r) + q] = cmul(o2, wB[1]);
            Ex[row * Sd + 4 * (12 + r) + q] = cmul(o3, wB[2]);
        }
        __syncthreads();

        // Stage C (stride 1) + diag(t), write back natural order
        #pragma unroll
        for (int r = 0; r < 4; r++) {
            float2 a  = Ex[row * Sd + 16 * q + 4 * r + 0];
            float2 b  = Ex[row * Sd + 16 * q + 4 * r + 1];
            float2 c2 = Ex[row * Sd + 16 * q + 4 * r + 2];
            float2 d2 = Ex[row * Sd + 16 * q + 4 * r + 3];
            float2 o0, o1, o2, o3;
            bfly4(a, b, c2, d2, o0, o1, o2, o3);
            int n0 = 4 * q + r;
            Ms[row * Sd + n0]      = cmul(o0, tS[n0]);
            Ms[row * Sd + n0 + 16] = cmul(o1, tS[n0 + 16]);
            Ms[row * Sd + n0 + 32] = cmul(o2, tS[n0 + 32]);
            Ms[row * Sd + n0 + 48] = cmul(o3, tS[n0 + 48]);
        }
        __syncthreads();
    }

    // ============ Convert M to SoA planes (over dead Ex+tS region) =========
    float* shf = (float*)sh;
    float* Mre = shf + 2 * Nn * Sd;             // float idx 8320, 4224 floats
    float* Mim = Mre + Nn * 66;                 // 4224 floats (holds -Im)
    float* Xr  = shf;                           // [64*64] over dead Ms (later)
    float* Xi  = shf + Nn * Nn;                 // [64*64]

    for (int idx = tid; idx < Nn * Nn; idx += 256) {
        int i = idx >> 6, j = idx & 63;
        float2 v = Ms[i * Sd + j];
        Mre[i * 66 + j] =  v.x;
        Mim[i * 66 + j] = -v.y;                 // pre-negated imag plane
    }
    __syncthreads();                            // Ms dead after this

    // =================== Phase B: apply (real part only) ==================
    const int tb = tid >> 4;            // 0..15 -> batch rows {4tb..4tb+3}
    const int ti = tid & 15;            // output cols {ti, +16, +32, +48}

    for (int bt = 0; bt < Bb / 64; ++bt) {
        for (int idx = tid; idx < Nn * Nn; idx += 256) {
            int r = idx >> 6, j = idx & 63;
            long long b = (long long)bt * 64 + r;
            long long g = ((b * Dd + d) * Ww + w) * Nn + j;
            Xr[r * 64 + j] = gldf(xr, g * xstride, nxr);
            Xi[r * 64 + j] = gldf(xi, g * xstride, nxi);
        }
        __syncthreads();

        unsigned long long acc[4][4];
        #pragma unroll
        for (int r = 0; r < 4; r++)
            #pragma unroll
            for (int c = 0; c < 4; c++)
                acc[r][c] = 0ull;

        #pragma unroll 4
        for (int jp = 0; jp < Nn / 2; ++jp) {
            unsigned long long xr2[4], xi2[4], mr2[4], mi2[4];
            #pragma unroll
            for (int r = 0; r < 4; r++) {
                xr2[r] = *(const unsigned long long*)
                         (Xr + (tb * 4 + r) * 64 + 2 * jp);
                xi2[r] = *(const unsigned long long*)
                         (Xi + (tb * 4 + r) * 64 + 2 * jp);
            }
            #pragma unroll
            for (int c = 0; c < 4; c++) {
                mr2[c] = *(const unsigned long long*)
                         (Mre + (ti + 16 * c) * 66 + 2 * jp);
                mi2[c] = *(const unsigned long long*)
                         (Mim + (ti + 16 * c) * 66 + 2 * jp);
            }
            #pragma unroll
            for (int r = 0; r < 4; r++)
                #pragma unroll
                for (int c = 0; c < 4; c++) {
                    ffma2(acc[r][c], xr2[r], mr2[c]);
                    ffma2(acc[r][c], xi2[r], mi2[c]);   // Mim pre-negated
                }
        }

        #pragma unroll
        for (int r = 0; r < 4; r++)
            #pragma unroll
            for (int c = 0; c < 4; c++) {
                float lo = __uint_as_float((unsigned)(acc[r][c] & 0xffffffffu));
                float hi = __uint_as_float((unsigned)(acc[r][c] >> 32));
                float re = lo + hi;
                long long b = (long long)bt * 64 + tb * 4 + r;
                int i = ti + 16 * c;
                long long g = ((b * Dd + d) * Ww + w) * Nn + i;
                if (g < nof) outf[g] = re;
            }
        __syncthreads();
    }
}

// ---------------------------------------------------------------------------
extern "C" void kernel_launch(void* const* d_in, const int* in_sizes, int n_in,
                              void* d_out, int out_size)
{
    const long long NX = (long long)Bb * Dd * Ww * Nn;   // 33,554,432
    const long long NV = (long long)Kk * Dd * Nn;        // 32,768
    const long long NW = Ww;                             // 128

    const float *x0 = 0, *x1 = 0, *vals = 0, *wls = 0;
    long long nx0 = 0, nx1 = 0, nv = 0, nw = 0;
    int xcomplex = 0;

    for (int pass = 0; pass < 2; ++pass) {
        long long mul = (pass == 0) ? 1 : 4;
        x0 = x1 = vals = wls = 0; nx0 = nx1 = nv = nw = 0; xcomplex = 0;
        int nxbuf = 0;
        for (int i = 0; i < n_in; i++) {
            long long s = (long long)in_sizes[i];
            const float* p = (const float*)d_in[i];
            if (!p) continue;
            if (s == NX * mul) {
                if (nxbuf == 0) { x0 = p; nx0 = NX; nxbuf = 1; }
                else if (nxbuf == 1) { x1 = p; nx1 = NX; nxbuf = 2; }
            } else if (s == 2 * NX * mul) {
                x0 = p; nx0 = 2 * NX; nxbuf = 2; xcomplex = 1;
            } else if (s == NV * mul) { if (!vals) { vals = p; nv = NV; } }
            else if (s == NW * mul)   { if (!wls)  { wls  = p; nw = NW; } }
        }
        if (nxbuf == 1 && vals && wls) {
            xcomplex = 1; nx0 = 2 * NX; x1 = 0; nxbuf = 2;
        }
        if (nxbuf == 2 && vals && wls) break;
        x0 = 0;
    }

    if (!(x0 && vals && wls) || !d_out) {
        long long n = (out_size > 4) ? (long long)out_size / 4 : 1;
        pic_probe<<<(unsigned)((n + 255) / 256), 256>>>((float*)d_out, n);
        return;
    }

    // d_out = out_size float32 (real part) — established R8.
    long long n_floats = ((long long)out_size < NX) ? (long long)out_size : NX;

    const float* xrp; const float* xip; long long nxr, nxi; int xstride;
    if (xcomplex) { xrp = x0; nxr = nx0; xip = x0 + 1; nxi = nx0 - 1; xstride = 2; }
    else          { xrp = x0; nxr = nx0; xip = x1;     nxi = nx1;     xstride = 1; }

    cudaFuncSetAttribute(pic_fused, cudaFuncAttributeMaxDynamicSharedMemorySize,
                         SMEM_BYTES);

    dim3 grid(Ww, Dd);
    pic_fused<<<grid, 256, SMEM_BYTES>>>(vals, nv, wls, nw,
                                         xrp, nxr, xip, nxi, xstride,
                                         (float*)d_out, n_floats);
}